// round 6
// baseline (speedup 1.0000x reference)
#include <cuda_runtime.h>
#include <stdint.h>

// Problem constants
#define Bb 128
#define Dd 128
#define Tt 2048
#define Cc 64
#define NTOT (Bb*Tt)            // 262144 rows

// K1 config: one block per batch row b, warp-specialized
#define G1    128
#define TH1   1024              // 512 consumers (warps 0-15) + 512 producers (16-31)
#define NCONS 512
#define JS    64                // t-columns per stage
#define NST   (Tt/JS)           // 32 stages
#define TSTR  65                // tile row stride (odd -> conflict-free)
#define NCPY  4                 // private acc copies (one per 128-consumer group)

// Named barriers (ids 1..4; 0 reserved for __syncthreads)
#define BAR_FULL0  1
#define BAR_FULL1  2
#define BAR_EMPTY0 3
#define BAR_EMPTY1 4
#define BSYNC(id)   asm volatile("bar.sync %0, %1;"   :: "r"(id), "r"(TH1) : "memory")
#define BARRIVE(id) asm volatile("bar.arrive %0, %1;" :: "r"(id), "r"(TH1) : "memory")

// Static device scratch (no allocations allowed)
__device__ float g_partial[(size_t)G1 * Cc * Dd];   // 4 MB per-block partials
__device__ int   g_pcnt[Cc * G1];                   // [c][g]
__device__ float g_psq[G1];
__device__ float g_sumsq;
__device__ float g_lpart[Cc];

// ---------------------------------------------------------------------------
// K1: warp-specialized streaming pass.
//  - producers (warps 16-31): LDG.128 stream -> double-buffered smem tile,
//    sumsq on the fly. Consumers (warps 0-15): column-owned smem accumulate
//    from tile into 4 private acc copies. Handshake: named bar arrive/sync.
// ---------------------------------------------------------------------------
__global__ void __launch_bounds__(TH1, 1)
k1_main(const float* __restrict__ feature, const int* __restrict__ lab32) {
    extern __shared__ float sm[];
    float* acc  = sm;                              // NCPY*8192 floats (128 KB)
    float* tile = sm + NCPY * Cc * Dd;             // 2 bufs * 128*65 (65 KB)
    int*   labs = (int*)(tile + 2 * Dd * TSTR);    // 2048 ints (8 KB)
    int*   cnt  = labs + Tt;                       // 64 ints
    float* red  = (float*)(cnt + Cc);              // 16 floats
    int*   sflag= (int*)(red + 16);                // 1 int

    const int tid = threadIdx.x;
    const int w = tid >> 5;
    const int l = tid & 31;
    const int b = blockIdx.x;

    // zero acc + cnt
    {
        float4* a4 = reinterpret_cast<float4*>(acc);
        const float4 z = make_float4(0.f, 0.f, 0.f, 0.f);
        #pragma unroll
        for (int k = 0; k < (NCPY * Cc * Dd) / 4 / TH1; ++k) a4[tid + k * TH1] = z;
        if (tid < Cc) cnt[tid] = 0;
        if (tid == 0) *sflag = 0;
    }
    __syncthreads();

    // Label-width probe over the FIRST 4096 int64 slots (word idx < 8192:
    // in-bounds for both widths). Values < 64 => genuine int64 buffer has
    // all-zero odd words.
    {
        int any = lab32[tid * 2 + 1] | lab32[(tid + TH1) * 2 + 1];
        #pragma unroll
        for (int o = 16; o > 0; o >>= 1) any |= __shfl_xor_sync(0xffffffff, any, o);
        if (l == 0 && any) atomicOr(sflag, 1);
    }
    __syncthreads();
    const int is64 = (*sflag == 0) ? 1 : 0;

    // preload this block's 2048 labels + histogram
    {
        const int base = b * Tt;
        #pragma unroll
        for (int k = 0; k < Tt / TH1; ++k) {
            int i = tid + k * TH1;
            int lab = is64 ? lab32[(base + i) * 2] : lab32[base + i];
            labs[i] = lab;
            atomicAdd(&cnt[lab], 1);
        }
    }
    __syncthreads();

    const float* fb = feature + (size_t)b * Dd * Tt;

    if (tid >= NCONS) {
        // ----------------- PRODUCER (warps 16-31) -----------------
        const int p  = tid - NCONS;                // 0..511
        const int d0 = p >> 4;                     // 0..31
        const int j0 = (p & 15) * 4;
        const float* base_g = fb + (size_t)d0 * Tt + j0;

        float sq = 0.0f;
        float4 R[4];
        #pragma unroll
        for (int k = 0; k < 4; ++k)
            R[k] = *reinterpret_cast<const float4*>(base_g + (size_t)k * 32 * Tt);

        for (int s = 0; s < NST; ++s) {
            const int buf = s & 1;
            if (s >= 2) BSYNC(BAR_EMPTY0 + buf);   // wait: consumers freed buf
            float* tb = tile + buf * (Dd * TSTR);
            #pragma unroll
            for (int k = 0; k < 4; ++k) {
                float4 v = R[k];
                sq += v.x * v.x + v.y * v.y + v.z * v.z + v.w * v.w;
                float* tp = tb + (d0 + 32 * k) * TSTR + j0;
                tp[0] = v.x; tp[1] = v.y; tp[2] = v.z; tp[3] = v.w;
            }
            __threadfence_block();
            BARRIVE(BAR_FULL0 + buf);              // publish buf
            if (s + 1 < NST) {
                const float* pg = base_g + (s + 1) * JS;
                #pragma unroll
                for (int k = 0; k < 4; ++k)
                    R[k] = *reinterpret_cast<const float4*>(pg + (size_t)k * 32 * Tt);
            }
        }
        #pragma unroll
        for (int o = 16; o > 0; o >>= 1) sq += __shfl_xor_sync(0xffffffff, sq, o);
        if (l == 0) red[w - 16] = sq;
    } else {
        // ----------------- CONSUMER (warps 0-15) -----------------
        const int grp = tid >> 7;                  // 0..3
        const int dd  = tid & 127;                 // owned column
        const int jb  = grp * 16;
        float* accg = acc + grp * (Cc * Dd);

        for (int s = 0; s < NST; ++s) {
            const int buf = s & 1;
            BSYNC(BAR_FULL0 + buf);                // wait: producers filled buf
            const float* tb = tile + buf * (Dd * TSTR);
            const int ls = s * JS + jb;
            #pragma unroll
            for (int jj = 0; jj < 16; ++jj) {
                const int lab = labs[ls + jj];
                accg[lab * Dd + dd] += tb[dd * TSTR + (jb + jj)];
            }
            BARRIVE(BAR_EMPTY0 + buf);             // release buf
        }
    }
    __syncthreads();

    // merge 4 copies -> per-block partials (non-atomic), all 1024 threads
    {
        float4* po = reinterpret_cast<float4*>(g_partial + (size_t)b * Cc * Dd);
        const float4* a0 = reinterpret_cast<const float4*>(acc);
        const float4* a1 = reinterpret_cast<const float4*>(acc + Cc * Dd);
        const float4* a2 = reinterpret_cast<const float4*>(acc + 2 * Cc * Dd);
        const float4* a3 = reinterpret_cast<const float4*>(acc + 3 * Cc * Dd);
        #pragma unroll
        for (int k = 0; k < (Cc * Dd) / 4 / TH1; ++k) {
            int i = tid + k * TH1;
            float4 x = a0[i], y = a1[i], z = a2[i], u = a3[i];
            x.x += y.x + z.x + u.x; x.y += y.y + z.y + u.y;
            x.z += y.z + z.z + u.z; x.w += y.w + z.w + u.w;
            po[i] = x;
        }
    }
    if (tid < Cc) g_pcnt[tid * G1 + b] = cnt[tid];
    if (tid == 0) {
        float s = 0.f;
        #pragma unroll
        for (int i = 0; i < 16; ++i) s += red[i];
        g_psq[b] = s;
    }
}

// ---------------------------------------------------------------------------
// KE: fused epilogue. Block c owns class c: folds count column + 128 partials
// (float4), computes difference + per-class loss term. Block 0 folds sumsq.
// ---------------------------------------------------------------------------
__global__ void kE_finish(const float* __restrict__ centers,
                          float* __restrict__ out) {
    __shared__ float4 sred[256];
    __shared__ float  sS[Dd];
    __shared__ int    scnt;
    __shared__ float  rterm[4];
    __shared__ float  rsq[4];

    const int c = blockIdx.x;
    const int t = threadIdx.x;                     // 256 threads
    const int w = t >> 5, l = t & 31;

    if (t == 0) scnt = 0;
    __syncthreads();

    if (t < G1) {
        int v = g_pcnt[c * G1 + t];
        #pragma unroll
        for (int o = 16; o > 0; o >>= 1) v += __shfl_xor_sync(0xffffffff, v, o);
        if (l == 0) atomicAdd(&scnt, v);
    }
    if (c == 0 && t >= 128) {
        float p = g_psq[t - 128];
        #pragma unroll
        for (int o = 16; o > 0; o >>= 1) p += __shfl_xor_sync(0xffffffff, p, o);
        if (l == 0) rsq[w - 4] = p;
    }

    {
        const float4* gp4 = reinterpret_cast<const float4*>(g_partial);
        const int d4 = t & 31;
        const int sl = t >> 5;
        float4 s = make_float4(0.f, 0.f, 0.f, 0.f);
        #pragma unroll
        for (int g = 0; g < G1 / 8; ++g) {
            float4 v = gp4[(size_t)(sl * (G1 / 8) + g) * 2048 + c * 32 + d4];
            s.x += v.x; s.y += v.y; s.z += v.z; s.w += v.w;
        }
        sred[t] = s;
    }
    __syncthreads();
    if (t < 32) {
        float4 s = sred[t];
        #pragma unroll
        for (int k = 1; k < 8; ++k) {
            float4 v = sred[t + 32 * k];
            s.x += v.x; s.y += v.y; s.z += v.z; s.w += v.w;
        }
        reinterpret_cast<float4*>(sS)[t] = s;
    }
    __syncthreads();

    float term = 0.0f;
    if (t < Dd) {
        const float sv  = sS[t];
        const float fc  = (float)scnt;
        const float ctr = centers[c * Dd + t];
        out[1 + c * Dd + t] = (fc * ctr - sv) / fmaxf(fc, 1.0f);
        term = fc * ctr * ctr - 2.0f * ctr * sv;
    }
    #pragma unroll
    for (int o = 16; o > 0; o >>= 1) term += __shfl_xor_sync(0xffffffff, term, o);
    if (l == 0 && w < 4) rterm[w] = term;
    __syncthreads();
    if (t == 0) {
        g_lpart[c] = rterm[0] + rterm[1] + rterm[2] + rterm[3];
        if (c == 0) g_sumsq = rsq[0] + rsq[1] + rsq[2] + rsq[3];
    }
}

// ---------------------------------------------------------------------------
// K4: final scalar loss
// ---------------------------------------------------------------------------
__global__ void k4_loss(float* __restrict__ out) {
    float ls = 0.f;
    #pragma unroll
    for (int i = 0; i < Cc; ++i) ls += g_lpart[i];
    out[0] = (g_sumsq + ls) / (float)((size_t)NTOT * Dd);
}

// ---------------------------------------------------------------------------
extern "C" void kernel_launch(void* const* d_in, const int* in_sizes, int n_in,
                              void* d_out, int out_size) {
    const float* feature = (const float*)d_in[0];
    const int*   lab32   = (const int*)d_in[1];   // width auto-detected in k1
    const float* centers = (const float*)d_in[2];
    float*       out     = (float*)d_out;

    const int smem_bytes = (NCPY * Cc * Dd + 2 * Dd * TSTR) * 4   // acc + 2 tiles
                         + Tt * 4 + Cc * 4 + 16 * 4 + 4;          // labs+cnt+red+flag
    cudaFuncSetAttribute(k1_main, cudaFuncAttributeMaxDynamicSharedMemorySize,
                         smem_bytes);

    k1_main<<<G1, TH1, smem_bytes>>>(feature, lab32);
    kE_finish<<<Cc, 256>>>(centers, out);
    k4_loss<<<1, 1>>>(out);
}

// round 7
// speedup vs baseline: 1.5106x; 1.5106x over previous
#include <cuda_runtime.h>
#include <stdint.h>

// Problem constants
#define Bb 128
#define Dd 128
#define Tt 2048
#define Cc 64
#define NTOT (Bb*Tt)            // 262144 rows

// K1 config: one block per batch row b, 1 block/SM
#define G1   128
#define TH1  512
#define JS   64                 // t-columns per stage
#define NST  (Tt/JS)            // 32 stages
#define TSTR 65                 // tile row stride (odd -> conflict-free)
#define NCPY 4                  // private acc copies (one per 128-thread group)
#define TILE (Dd*TSTR)

// Static device scratch (no allocations allowed)
__device__ float g_partial[(size_t)G1 * Cc * Dd];   // 4 MB per-block partials
__device__ int   g_pcnt[Cc * G1];                   // [c][g]
__device__ float g_psq[G1];
__device__ float g_sumsq;
__device__ float g_lpart[Cc];

// ---------------------------------------------------------------------------
// K1: streaming pass, depth-2 software pipeline, ONE sync per stage.
// Phase s: commit regs(stage s) -> tile[s&1]; LDG regs <- stage s+2;
//          accumulate stage s-1 from tile[(s-1)&1]; __syncthreads.
// ---------------------------------------------------------------------------
__global__ void __launch_bounds__(TH1, 1)
k1_main(const float* __restrict__ feature, const int* __restrict__ lab32) {
    extern __shared__ float sm[];
    float* acc  = sm;                              // NCPY*8192 floats (128 KB)
    float* tile = sm + NCPY * Cc * Dd;             // 2 bufs * 128*65 (65 KB)
    int*   labs = (int*)(tile + 2 * TILE);         // 2048 ints (8 KB)
    int*   cnt  = labs + Tt;                       // 64 ints
    float* red  = (float*)(cnt + Cc);              // 16 floats
    int*   sflag= (int*)(red + 16);                // 1 int

    const int tid = threadIdx.x;
    const int w = tid >> 5;
    const int l = tid & 31;
    const int grp = tid >> 7;                      // 0..3
    const int dd  = tid & 127;                     // owned column
    const int b   = blockIdx.x;

    // zero acc + cnt
    {
        float4* a4 = reinterpret_cast<float4*>(acc);
        const float4 z = make_float4(0.f, 0.f, 0.f, 0.f);
        #pragma unroll
        for (int k = 0; k < (NCPY * Cc * Dd) / 4 / TH1; ++k) a4[tid + k * TH1] = z;
        if (tid < Cc) cnt[tid] = 0;
        if (tid == 0) *sflag = 0;
    }
    __syncthreads();

    // Label-width probe: odd words of the FIRST 4096 int64 slots (word idx
    // < 8192, in-bounds for both widths). Values < 64 => genuine int64
    // buffer has all-zero odd words.
    {
        int any = 0;
        #pragma unroll
        for (int k = 0; k < 4096 / TH1; ++k)
            any |= lab32[(tid + k * TH1) * 2 + 1];
        #pragma unroll
        for (int o = 16; o > 0; o >>= 1) any |= __shfl_xor_sync(0xffffffff, any, o);
        if (l == 0 && any) atomicOr(sflag, 1);
    }
    __syncthreads();
    const int is64 = (*sflag == 0) ? 1 : 0;

    // preload this block's 2048 labels + histogram
    {
        const int base = b * Tt;
        #pragma unroll
        for (int k = 0; k < Tt / TH1; ++k) {
            int i = tid + k * TH1;
            int lab = is64 ? lab32[(base + i) * 2] : lab32[base + i];
            labs[i] = lab;
            atomicAdd(&cnt[lab], 1);
        }
    }
    __syncthreads();

    const float* fb = feature + (size_t)b * Dd * Tt;
    const int d0 = tid >> 4;                       // base row (0..31)
    const int j0 = (tid & 15) * 4;                 // float4 column
    const float* base_g = fb + (size_t)d0 * Tt + j0;
    float* accg = acc + grp * (Cc * Dd);
    const int jb = grp * 16;

    float sq = 0.0f;
    float4 A[4], B[4];

    #pragma unroll
    for (int k = 0; k < 4; ++k) {
        A[k] = *reinterpret_cast<const float4*>(base_g + (size_t)k * 32 * Tt);
        B[k] = *reinterpret_cast<const float4*>(base_g + JS + (size_t)k * 32 * Tt);
    }

    #define COMMIT(RS, TB)                                                     \
        {                                                                      \
            float* tb_ = (TB);                                                 \
            _Pragma("unroll")                                                  \
            for (int k = 0; k < 4; ++k) {                                      \
                float4 v = RS[k];                                              \
                sq += v.x * v.x + v.y * v.y + v.z * v.z + v.w * v.w;           \
                float* tp = tb_ + (d0 + 32 * k) * TSTR + j0;                   \
                tp[0] = v.x; tp[1] = v.y; tp[2] = v.z; tp[3] = v.w;            \
            }                                                                  \
        }
    #define LOADR(RS, S)                                                       \
        {                                                                      \
            const float* pg_ = base_g + (S) * JS;                              \
            _Pragma("unroll")                                                  \
            for (int k = 0; k < 4; ++k)                                        \
                RS[k] = *reinterpret_cast<const float4*>(pg_ + (size_t)k * 32 * Tt); \
        }
    #define ACCUM(S, TB)                                                       \
        {                                                                      \
            const float* tb_ = (TB);                                           \
            const int ls_ = (S) * JS + jb;                                     \
            _Pragma("unroll")                                                  \
            for (int jj = 0; jj < 16; ++jj) {                                  \
                const int lab_ = labs[ls_ + jj];                               \
                accg[lab_ * Dd + dd] += tb_[dd * TSTR + (jb + jj)];            \
            }                                                                  \
        }

    for (int s = 0; s < NST; s += 2) {
        // phase s (even): commit A(s) -> buf0, prefetch A <- s+2, accum s-1 (buf1)
        COMMIT(A, tile);
        if (s + 2 < NST) LOADR(A, s + 2);
        if (s > 0) ACCUM(s - 1, tile + TILE);
        __syncthreads();
        // phase s+1 (odd): commit B(s+1) -> buf1, prefetch B <- s+3, accum s (buf0)
        COMMIT(B, tile + TILE);
        if (s + 3 < NST) LOADR(B, s + 3);
        ACCUM(s, tile);
        __syncthreads();
    }
    ACCUM(NST - 1, tile + TILE);
    __syncthreads();

    // merge 4 copies -> per-block partials (non-atomic)
    {
        float4* po = reinterpret_cast<float4*>(g_partial + (size_t)b * Cc * Dd);
        const float4* a0 = reinterpret_cast<const float4*>(acc);
        const float4* a1 = reinterpret_cast<const float4*>(acc + Cc * Dd);
        const float4* a2 = reinterpret_cast<const float4*>(acc + 2 * Cc * Dd);
        const float4* a3 = reinterpret_cast<const float4*>(acc + 3 * Cc * Dd);
        #pragma unroll
        for (int k = 0; k < (Cc * Dd) / 4 / TH1; ++k) {
            int i = tid + k * TH1;
            float4 x = a0[i], y = a1[i], z = a2[i], u = a3[i];
            x.x += y.x + z.x + u.x; x.y += y.y + z.y + u.y;
            x.z += y.z + z.z + u.z; x.w += y.w + z.w + u.w;
            po[i] = x;
        }
    }
    if (tid < Cc) g_pcnt[tid * G1 + b] = cnt[tid];

    #pragma unroll
    for (int o = 16; o > 0; o >>= 1) sq += __shfl_xor_sync(0xffffffff, sq, o);
    if (l == 0) red[w] = sq;
    __syncthreads();
    if (tid == 0) {
        float s = 0.f;
        #pragma unroll
        for (int i = 0; i < 16; ++i) s += red[i];
        g_psq[b] = s;
    }
}

// ---------------------------------------------------------------------------
// KE: fused epilogue. Block c owns class c: folds count column + 128 partials
// (float4), computes difference + per-class loss term. Block 0 folds sumsq.
// ---------------------------------------------------------------------------
__global__ void kE_finish(const float* __restrict__ centers,
                          float* __restrict__ out) {
    __shared__ float4 sred[256];
    __shared__ float  sS[Dd];
    __shared__ int    scnt;
    __shared__ float  rterm[4];
    __shared__ float  rsq[4];

    const int c = blockIdx.x;
    const int t = threadIdx.x;                     // 256 threads
    const int w = t >> 5, l = t & 31;

    if (t == 0) scnt = 0;
    __syncthreads();

    if (t < G1) {
        int v = g_pcnt[c * G1 + t];
        #pragma unroll
        for (int o = 16; o > 0; o >>= 1) v += __shfl_xor_sync(0xffffffff, v, o);
        if (l == 0) atomicAdd(&scnt, v);
    }
    if (c == 0 && t >= 128) {
        float p = g_psq[t - 128];
        #pragma unroll
        for (int o = 16; o > 0; o >>= 1) p += __shfl_xor_sync(0xffffffff, p, o);
        if (l == 0) rsq[w - 4] = p;
    }

    {
        const float4* gp4 = reinterpret_cast<const float4*>(g_partial);
        const int d4 = t & 31;
        const int sl = t >> 5;
        float4 s = make_float4(0.f, 0.f, 0.f, 0.f);
        #pragma unroll
        for (int g = 0; g < G1 / 8; ++g) {
            float4 v = gp4[(size_t)(sl * (G1 / 8) + g) * 2048 + c * 32 + d4];
            s.x += v.x; s.y += v.y; s.z += v.z; s.w += v.w;
        }
        sred[t] = s;
    }
    __syncthreads();
    if (t < 32) {
        float4 s = sred[t];
        #pragma unroll
        for (int k = 1; k < 8; ++k) {
            float4 v = sred[t + 32 * k];
            s.x += v.x; s.y += v.y; s.z += v.z; s.w += v.w;
        }
        reinterpret_cast<float4*>(sS)[t] = s;
    }
    __syncthreads();

    float term = 0.0f;
    if (t < Dd) {
        const float sv  = sS[t];
        const float fc  = (float)scnt;
        const float ctr = centers[c * Dd + t];
        out[1 + c * Dd + t] = (fc * ctr - sv) / fmaxf(fc, 1.0f);
        term = fc * ctr * ctr - 2.0f * ctr * sv;
    }
    #pragma unroll
    for (int o = 16; o > 0; o >>= 1) term += __shfl_xor_sync(0xffffffff, term, o);
    if (l == 0 && w < 4) rterm[w] = term;
    __syncthreads();
    if (t == 0) {
        g_lpart[c] = rterm[0] + rterm[1] + rterm[2] + rterm[3];
        if (c == 0) g_sumsq = rsq[0] + rsq[1] + rsq[2] + rsq[3];
    }
}

// ---------------------------------------------------------------------------
// K4: final scalar loss
// ---------------------------------------------------------------------------
__global__ void k4_loss(float* __restrict__ out) {
    float ls = 0.f;
    #pragma unroll
    for (int i = 0; i < Cc; ++i) ls += g_lpart[i];
    out[0] = (g_sumsq + ls) / (float)((size_t)NTOT * Dd);
}

// ---------------------------------------------------------------------------
extern "C" void kernel_launch(void* const* d_in, const int* in_sizes, int n_in,
                              void* d_out, int out_size) {
    const float* feature = (const float*)d_in[0];
    const int*   lab32   = (const int*)d_in[1];   // width auto-detected in k1
    const float* centers = (const float*)d_in[2];
    float*       out     = (float*)d_out;

    const int smem_bytes = (NCPY * Cc * Dd + 2 * TILE) * 4      // acc + 2 tiles
                         + Tt * 4 + Cc * 4 + 16 * 4 + 4;        // labs+cnt+red+flag
    cudaFuncSetAttribute(k1_main, cudaFuncAttributeMaxDynamicSharedMemorySize,
                         smem_bytes);

    k1_main<<<G1, TH1, smem_bytes>>>(feature, lab32);
    kE_finish<<<Cc, 256>>>(centers, out);
    k4_loss<<<1, 1>>>(out);
}